// round 4
// baseline (speedup 1.0000x reference)
#include <cuda_runtime.h>
#include <math.h>

// Problem constants (fixed by the dataset)
#define NN  50000
#define EE  800000
#define FIN 128
#define HH  128
#define CC  64

// ---------------- device scratch ------------------------------------------------
__device__ int   g_icnt[NN];        // in-degree
__device__ int   g_rowp[NN + 1];    // CSR row offsets (by dst)
__device__ int   g_cur [NN];        // bin cursors
__device__ int   g_srcs[EE];        // src node ids sorted by dst
__device__ float g_agg [NN * FIN];  // mean_aggr(x)       (layer 1)
__device__ float g_h   [NN * HH];   // relu(norm(sage1))
__device__ float g_h2  [NN * HH];   // relu([x,h] @ Wl1^T + bl1)
__device__ float g_t2  [NN * CC];   // h2 @ W2_l^T  (pre-transformed; mean commutes)
__device__ float g_r2  [NN * CC];   // h2 @ W2_r^T

// ---------------- degree count ----------------------------------------------------
__global__ void k_zero() {
    int i = blockIdx.x * blockDim.x + threadIdx.x;
    if (i < NN) g_icnt[i] = 0;
}

__global__ void k_count(const int* __restrict__ ei) {
    int e = blockIdx.x * blockDim.x + threadIdx.x;
    if (e < EE) atomicAdd(&g_icnt[ei[EE + e]], 1);
}

// ---------------- single-block 2-level exclusive scan ------------------------------
__global__ __launch_bounds__(1024) void k_scan() {
    __shared__ int sm[1024];
    const int t  = threadIdx.x;
    const int CH = (NN + 1023) / 1024;
    int beg = t * CH;
    int end = min(beg + CH, NN);
    int s = 0;
    for (int i = beg; i < end; i++) s += g_icnt[i];
    sm[t] = s;
    __syncthreads();
#pragma unroll
    for (int o = 1; o < 1024; o <<= 1) {
        int u = (t >= o) ? sm[t - o] : 0;
        __syncthreads();
        sm[t] += u;
        __syncthreads();
    }
    int run = sm[t] - s;
    for (int i = beg; i < end; i++) {
        g_rowp[i] = run;
        g_cur[i]  = run;
        run += g_icnt[i];
    }
    if (t == 1023) g_rowp[NN] = EE;
}

// ---------------- bin: srcs sorted by dst (2 edges/thread) --------------------------
__global__ void k_bin(const int* __restrict__ ei) {
    int e0 = (blockIdx.x * blockDim.x + threadIdx.x) * 2;
#pragma unroll
    for (int q = 0; q < 2; q++) {
        int e = e0 + q;
        if (e < EE) {
            int src = ei[e];
            int dst = ei[EE + e];
            int p = atomicAdd(&g_cur[dst], 1);
            g_srcs[p] = src;
        }
    }
}

// ---------------- layer-1 mean aggregation: warp per node, unroll-2 -----------------
__global__ void k_aggr1(const float* __restrict__ x) {
    int node = (blockIdx.x * blockDim.x + threadIdx.x) >> 5;
    int lane = threadIdx.x & 31;
    if (node >= NN) return;
    int beg = g_rowp[node], end = g_rowp[node + 1];
    float4 a0 = make_float4(0.f, 0.f, 0.f, 0.f);
    float4 a1 = make_float4(0.f, 0.f, 0.f, 0.f);
    int i = beg;
    for (; i + 1 < end; i += 2) {
        int s0 = __ldg(&g_srcs[i]);
        int s1 = __ldg(&g_srcs[i + 1]);
        float4 v0 = ((const float4*)(x + (size_t)s0 * FIN))[lane];
        float4 v1 = ((const float4*)(x + (size_t)s1 * FIN))[lane];
        a0.x += v0.x; a0.y += v0.y; a0.z += v0.z; a0.w += v0.w;
        a1.x += v1.x; a1.y += v1.y; a1.z += v1.z; a1.w += v1.w;
    }
    if (i < end) {
        int s0 = __ldg(&g_srcs[i]);
        float4 v0 = ((const float4*)(x + (size_t)s0 * FIN))[lane];
        a0.x += v0.x; a0.y += v0.y; a0.z += v0.z; a0.w += v0.w;
    }
    float inv = 1.0f / fmaxf((float)(end - beg), 1.0f);
    float4 acc;
    acc.x = (a0.x + a1.x) * inv; acc.y = (a0.y + a1.y) * inv;
    acc.z = (a0.z + a1.z) * inv; acc.w = (a0.w + a1.w) * inv;
    ((float4*)(g_agg + (size_t)node * FIN))[lane] = acc;
}

// ---------------- tf32 helpers ----------------------------------------------------
__device__ __forceinline__ unsigned f2tf32(float f) {
    unsigned r;
    asm("cvt.rna.tf32.f32 %0, %1;" : "=r"(r) : "f"(f));
    return r;
}

#define MMA_TF32(d, a, b)                                                       \
    asm volatile("mma.sync.aligned.m16n8k8.row.col.f32.tf32.tf32.f32 "          \
                 "{%0,%1,%2,%3}, {%4,%5,%6,%7}, {%8,%9}, {%0,%1,%2,%3};"        \
                 : "+f"(d[0]), "+f"(d[1]), "+f"(d[2]), "+f"(d[3])               \
                 : "r"(a[0]), "r"(a[1]), "r"(a[2]), "r"(a[3]),                  \
                   "r"(b[0]), "r"(b[1]))

// ---------------- tensor-core tf32 SGEMM, 128x128 tile, double-buffered ------------
// MODE 0: g_h  = relu( norm( [agg | x] @ [W1_l|W1_r]^T + b1 ) )   K=256
// MODE 1: g_h2 = relu( [x | h] @ Wl1^T + bl1 )                    K=256
// MODE 2: [g_t2|g_r2] = g_h2 @ [W2_l ; W2_r]^T                    K=128
#define SAS 136                     // 136 % 32 == 8 -> conflict-free fragment LDS
#define BUFW (32 * SAS)             // words per buffer
#define GEMM_SMEM_BYTES ((4 * BUFW + 512) * 4)

template <int MODE>
__launch_bounds__(256)
__global__ void k_gemm(const float* __restrict__ X,
                       const float* __restrict__ WA,
                       const float* __restrict__ WB,
                       const float* __restrict__ bias) {
    constexpr int KTOT = (MODE == 2) ? 128 : 256;
    constexpr int NC   = KTOT / 32;

    extern __shared__ unsigned smem[];
    unsigned* Ab[2] = { smem,            smem + BUFW };
    unsigned* Wb[2] = { smem + 2 * BUFW, smem + 3 * BUFW };
    float*    rss   = (float*)(smem + 4 * BUFW);

    const int tid  = threadIdx.x;
    const int lane = tid & 31;
    const int w    = tid >> 5;
    const int wm   = w & 1;        // 0..1 (64 rows each)
    const int wn   = w >> 1;       // 0..3 (32 cols each)
    const int qid  = lane >> 2;    // 0..7
    const int tig  = lane & 3;     // 0..3
    const int m0   = blockIdx.x * 128;

    float4 ra[4], rw[4];

    auto loadA = [&](int k0) {
#pragma unroll
        for (int p = 0; p < 4; p++) {
            int f4 = tid + p * 256;
            int n  = f4 >> 3;
            int k  = k0 + (f4 & 7) * 4;
            int gm = m0 + n;
            float4 v = make_float4(0.f, 0.f, 0.f, 0.f);
            if (gm < NN) {
                if (MODE == 0) {
                    if (k < 128) v = *(const float4*)(g_agg + (size_t)gm * 128 + k);
                    else         v = *(const float4*)(X     + (size_t)gm * 128 + (k - 128));
                } else if (MODE == 1) {
                    if (k < 128) v = *(const float4*)(X   + (size_t)gm * 128 + k);
                    else         v = *(const float4*)(g_h + (size_t)gm * 128 + (k - 128));
                } else {
                    v = *(const float4*)(g_h2 + (size_t)gm * 128 + k);
                }
            }
            ra[p] = v;
        }
    };
    auto loadW = [&](int k0) {
#pragma unroll
        for (int p = 0; p < 4; p++) {
            int f4 = tid + p * 256;
            int j  = f4 >> 3;
            int k  = k0 + (f4 & 7) * 4;
            float4 v;
            if (MODE == 0) {
                v = (k < 128) ? *(const float4*)(WA + j * 128 + k)
                              : *(const float4*)(WB + j * 128 + (k - 128));
            } else if (MODE == 1) {
                v = *(const float4*)(WA + j * 256 + k);
            } else {
                v = (j < 64) ? *(const float4*)(WA + j * 128 + k)
                             : *(const float4*)(WB + (j - 64) * 128 + k);
            }
            rw[p] = v;
        }
    };
    auto storeAW = [&](int buf) {
        unsigned* Ad = Ab[buf];
        unsigned* Wd = Wb[buf];
#pragma unroll
        for (int p = 0; p < 4; p++) {
            int f4 = tid + p * 256;
            int n  = f4 >> 3;
            int kk = (f4 & 7) * 4;
            Ad[(kk + 0) * SAS + n] = f2tf32(ra[p].x);
            Ad[(kk + 1) * SAS + n] = f2tf32(ra[p].y);
            Ad[(kk + 2) * SAS + n] = f2tf32(ra[p].z);
            Ad[(kk + 3) * SAS + n] = f2tf32(ra[p].w);
            Wd[(kk + 0) * SAS + n] = f2tf32(rw[p].x);
            Wd[(kk + 1) * SAS + n] = f2tf32(rw[p].y);
            Wd[(kk + 2) * SAS + n] = f2tf32(rw[p].z);
            Wd[(kk + 3) * SAS + n] = f2tf32(rw[p].w);
        }
    };

    float acc[4][4][4];
#pragma unroll
    for (int mt = 0; mt < 4; mt++)
#pragma unroll
        for (int nt = 0; nt < 4; nt++)
#pragma unroll
            for (int c = 0; c < 4; c++) acc[mt][nt][c] = 0.f;

    // prologue
    loadA(0); loadW(0);
    storeAW(0);
    __syncthreads();

    for (int c = 0; c < NC; c++) {
        const unsigned* As = Ab[c & 1];
        const unsigned* Ws = Wb[c & 1];
        const bool more = (c + 1 < NC);
        if (more) { loadA((c + 1) * 32); loadW((c + 1) * 32); }

#pragma unroll
        for (int ks = 0; ks < 4; ks++) {
            const int kr = ks * 8 + tig;
            unsigned a[4][4];
#pragma unroll
            for (int mt = 0; mt < 4; mt++) {
                int r0 = wm * 64 + mt * 16 + qid;
                a[mt][0] = As[kr * SAS + r0];
                a[mt][1] = As[kr * SAS + r0 + 8];
                a[mt][2] = As[(kr + 4) * SAS + r0];
                a[mt][3] = As[(kr + 4) * SAS + r0 + 8];
            }
            unsigned b[4][2];
#pragma unroll
            for (int nt = 0; nt < 4; nt++) {
                int c0 = wn * 32 + nt * 8 + qid;
                b[nt][0] = Ws[kr * SAS + c0];
                b[nt][1] = Ws[(kr + 4) * SAS + c0];
            }
#pragma unroll
            for (int mt = 0; mt < 4; mt++)
#pragma unroll
                for (int nt = 0; nt < 4; nt++)
                    MMA_TF32(acc[mt][nt], a[mt], b[nt]);
        }

        if (more) storeAW((c + 1) & 1);
        __syncthreads();
    }

    // ---------------- epilogue ----------------
    if (MODE == 0 || MODE == 1) {
#pragma unroll
        for (int nt = 0; nt < 4; nt++) {
            float2 bv = *(const float2*)(bias + wn * 32 + nt * 8 + tig * 2);
#pragma unroll
            for (int mt = 0; mt < 4; mt++) {
                acc[mt][nt][0] += bv.x; acc[mt][nt][1] += bv.y;
                acc[mt][nt][2] += bv.x; acc[mt][nt][3] += bv.y;
            }
        }
    }

    if (MODE == 0) {
        float ssl[4][2];
#pragma unroll
        for (int mt = 0; mt < 4; mt++) {
            float s0 = 0.f, s1 = 0.f;
#pragma unroll
            for (int nt = 0; nt < 4; nt++) {
                s0 += acc[mt][nt][0] * acc[mt][nt][0] + acc[mt][nt][1] * acc[mt][nt][1];
                s1 += acc[mt][nt][2] * acc[mt][nt][2] + acc[mt][nt][3] * acc[mt][nt][3];
            }
            s0 += __shfl_xor_sync(0xffffffffu, s0, 1);
            s0 += __shfl_xor_sync(0xffffffffu, s0, 2);
            s1 += __shfl_xor_sync(0xffffffffu, s1, 1);
            s1 += __shfl_xor_sync(0xffffffffu, s1, 2);
            ssl[mt][0] = s0; ssl[mt][1] = s1;
        }
        if (tig == 0) {
#pragma unroll
            for (int mt = 0; mt < 4; mt++) {
                int r0 = wm * 64 + mt * 16 + qid;
                rss[(r0)     * 4 + wn] = ssl[mt][0];
                rss[(r0 + 8) * 4 + wn] = ssl[mt][1];
            }
        }
        __syncthreads();
#pragma unroll
        for (int mt = 0; mt < 4; mt++) {
#pragma unroll
            for (int h = 0; h < 2; h++) {
                int r = wm * 64 + mt * 16 + qid + h * 8;
                float ss = rss[r * 4 + 0] + rss[r * 4 + 1] + rss[r * 4 + 2] + rss[r * 4 + 3];
                float sc = 1.0f / fmaxf(sqrtf(ss), 1e-12f);
                int gm = m0 + r;
                if (gm < NN) {
#pragma unroll
                    for (int nt = 0; nt < 4; nt++) {
                        float2 o;
                        o.x = fmaxf(acc[mt][nt][h * 2 + 0] * sc, 0.f);
                        o.y = fmaxf(acc[mt][nt][h * 2 + 1] * sc, 0.f);
                        *(float2*)(g_h + (size_t)gm * 128 + wn * 32 + nt * 8 + tig * 2) = o;
                    }
                }
            }
        }
    } else if (MODE == 1) {
#pragma unroll
        for (int mt = 0; mt < 4; mt++) {
#pragma unroll
            for (int h = 0; h < 2; h++) {
                int gm = m0 + wm * 64 + mt * 16 + qid + h * 8;
                if (gm < NN) {
#pragma unroll
                    for (int nt = 0; nt < 4; nt++) {
                        float2 o;
                        o.x = fmaxf(acc[mt][nt][h * 2 + 0], 0.f);
                        o.y = fmaxf(acc[mt][nt][h * 2 + 1], 0.f);
                        *(float2*)(g_h2 + (size_t)gm * 128 + wn * 32 + nt * 8 + tig * 2) = o;
                    }
                }
            }
        }
    } else {
        float* dstbuf = (wn < 2) ? g_t2 : g_r2;
        int coff0 = (wn < 2) ? wn * 32 : (wn - 2) * 32;
#pragma unroll
        for (int mt = 0; mt < 4; mt++) {
#pragma unroll
            for (int h = 0; h < 2; h++) {
                int gm = m0 + wm * 64 + mt * 16 + qid + h * 8;
                if (gm < NN) {
#pragma unroll
                    for (int nt = 0; nt < 4; nt++) {
                        float2 o = make_float2(acc[mt][nt][h * 2 + 0], acc[mt][nt][h * 2 + 1]);
                        *(float2*)(dstbuf + (size_t)gm * 64 + coff0 + nt * 8 + tig * 2) = o;
                    }
                }
            }
        }
    }
}

// ---------------- final: gather t2, out = norm( mean + b2 + r2 ), warp/node ---------
__global__ void k_out(const float* __restrict__ b2, float* __restrict__ out) {
    int node = (blockIdx.x * blockDim.x + threadIdx.x) >> 5;
    int lane = threadIdx.x & 31;
    if (node >= NN) return;
    int beg = g_rowp[node], end = g_rowp[node + 1];
    float2 a0 = make_float2(0.f, 0.f);
    float2 a1 = make_float2(0.f, 0.f);
    int i = beg;
    for (; i + 1 < end; i += 2) {
        int s0 = __ldg(&g_srcs[i]);
        int s1 = __ldg(&g_srcs[i + 1]);
        float2 v0 = ((const float2*)(g_t2 + (size_t)s0 * CC))[lane];
        float2 v1 = ((const float2*)(g_t2 + (size_t)s1 * CC))[lane];
        a0.x += v0.x; a0.y += v0.y;
        a1.x += v1.x; a1.y += v1.y;
    }
    if (i < end) {
        int s0 = __ldg(&g_srcs[i]);
        float2 v0 = ((const float2*)(g_t2 + (size_t)s0 * CC))[lane];
        a0.x += v0.x; a0.y += v0.y;
    }
    float inv = 1.0f / fmaxf((float)(end - beg), 1.0f);
    float2 r  = ((const float2*)(g_r2 + (size_t)node * CC))[lane];
    float2 bb = ((const float2*)b2)[lane];
    float v0 = (a0.x + a1.x) * inv + bb.x + r.x;
    float v1 = (a0.y + a1.y) * inv + bb.y + r.y;
    float ss = v0 * v0 + v1 * v1;
#pragma unroll
    for (int o = 16; o >= 1; o >>= 1) ss += __shfl_xor_sync(0xffffffffu, ss, o);
    float sc = 1.0f / fmaxf(sqrtf(ss), 1e-12f);
    ((float2*)(out + (size_t)node * CC))[lane] = make_float2(v0 * sc, v1 * sc);
}

// ---------------- launch ------------------------------------------------------------
extern "C" void kernel_launch(void* const* d_in, const int* in_sizes, int n_in,
                              void* d_out, int out_size) {
    const float* x    = (const float*)d_in[0];
    const int*   ei   = (const int*)  d_in[1];
    const float* W1_l = (const float*)d_in[2];
    const float* b1   = (const float*)d_in[3];
    const float* W1_r = (const float*)d_in[4];
    const float* Wl1  = (const float*)d_in[5];
    const float* bl1  = (const float*)d_in[6];
    const float* W2_l = (const float*)d_in[7];
    const float* b2   = (const float*)d_in[8];
    const float* W2_r = (const float*)d_in[9];
    float* out = (float*)d_out;

    static bool attr_done = false;
    if (!attr_done) {
        cudaFuncSetAttribute(k_gemm<0>, cudaFuncAttributeMaxDynamicSharedMemorySize, GEMM_SMEM_BYTES);
        cudaFuncSetAttribute(k_gemm<1>, cudaFuncAttributeMaxDynamicSharedMemorySize, GEMM_SMEM_BYTES);
        cudaFuncSetAttribute(k_gemm<2>, cudaFuncAttributeMaxDynamicSharedMemorySize, GEMM_SMEM_BYTES);
        attr_done = true;
    }

    k_zero  <<<(NN + 255) / 256, 256>>>();
    k_count <<<(EE + 255) / 256, 256>>>(ei);
    k_scan  <<<1, 1024>>>();
    k_bin   <<<(EE / 2 + 255) / 256, 256>>>(ei);
    k_aggr1 <<<(NN * 32 + 255) / 256, 256>>>(x);
    k_gemm<0><<<(NN + 127) / 128, 256, GEMM_SMEM_BYTES>>>(x, W1_l, W1_r, b1);
    k_gemm<1><<<(NN + 127) / 128, 256, GEMM_SMEM_BYTES>>>(x, Wl1, (const float*)nullptr, bl1);
    k_gemm<2><<<(NN + 127) / 128, 256, GEMM_SMEM_BYTES>>>((const float*)nullptr, W2_l, W2_r, (const float*)nullptr);
    k_out   <<<(NN * 32 + 255) / 256, 256>>>(b2, out);
}

// round 6
// speedup vs baseline: 1.3616x; 1.3616x over previous
#include <cuda_runtime.h>
#include <cuda_fp16.h>
#include <math.h>

// Problem constants (fixed by the dataset)
#define NN  50000
#define EE  800000
#define FIN 128
#define HH  128
#define CC  64

// ---------------- device scratch ------------------------------------------------
__device__ int   g_icnt[NN];        // in-degree
__device__ int   g_rowp[NN + 1];    // CSR row offsets (by dst)
__device__ int   g_cur [NN];        // bin cursors
__device__ int   g_srcs[EE];        // src node ids sorted by dst
__device__ float g_agg [NN * FIN];  // mean_aggr(x)       (layer 1)
__device__ float g_h   [NN * HH];   // relu(norm(sage1))
__device__ float g_h2  [NN * HH];   // relu([x,h] @ Wl1^T + bl1)
__device__ float g_t2  [NN * CC];   // h2 @ W2_l^T  (pre-transformed; mean commutes)
__device__ float g_r2  [NN * CC];   // h2 @ W2_r^T

// ---------------- degree count ----------------------------------------------------
__global__ void k_zero() {
    int i = blockIdx.x * blockDim.x + threadIdx.x;
    if (i < NN) g_icnt[i] = 0;
}

__global__ void k_count(const int* __restrict__ ei) {
    int e = blockIdx.x * blockDim.x + threadIdx.x;
    if (e < EE) atomicAdd(&g_icnt[ei[EE + e]], 1);
}

// ---------------- single-block 2-level exclusive scan ------------------------------
__global__ __launch_bounds__(1024) void k_scan() {
    __shared__ int sm[1024];
    const int t  = threadIdx.x;
    const int CH = (NN + 1023) / 1024;
    int beg = t * CH;
    int end = min(beg + CH, NN);
    int s = 0;
    for (int i = beg; i < end; i++) s += g_icnt[i];
    sm[t] = s;
    __syncthreads();
#pragma unroll
    for (int o = 1; o < 1024; o <<= 1) {
        int u = (t >= o) ? sm[t - o] : 0;
        __syncthreads();
        sm[t] += u;
        __syncthreads();
    }
    int run = sm[t] - s;
    for (int i = beg; i < end; i++) {
        g_rowp[i] = run;
        g_cur[i]  = run;
        run += g_icnt[i];
    }
    if (t == 1023) g_rowp[NN] = EE;
}

// ---------------- bin: srcs sorted by dst (2 edges/thread) --------------------------
__global__ void k_bin(const int* __restrict__ ei) {
    int e0 = (blockIdx.x * blockDim.x + threadIdx.x) * 2;
#pragma unroll
    for (int q = 0; q < 2; q++) {
        int e = e0 + q;
        if (e < EE) {
            int src = ei[e];
            int dst = ei[EE + e];
            int p = atomicAdd(&g_cur[dst], 1);
            g_srcs[p] = src;
        }
    }
}

// ---------------- layer-1 mean aggregation: warp per node, unroll-2 -----------------
__global__ void k_aggr1(const float* __restrict__ x) {
    int node = (blockIdx.x * blockDim.x + threadIdx.x) >> 5;
    int lane = threadIdx.x & 31;
    if (node >= NN) return;
    int beg = g_rowp[node], end = g_rowp[node + 1];
    float4 a0 = make_float4(0.f, 0.f, 0.f, 0.f);
    float4 a1 = make_float4(0.f, 0.f, 0.f, 0.f);
    int i = beg;
    for (; i + 1 < end; i += 2) {
        int s0 = __ldg(&g_srcs[i]);
        int s1 = __ldg(&g_srcs[i + 1]);
        float4 v0 = ((const float4*)(x + (size_t)s0 * FIN))[lane];
        float4 v1 = ((const float4*)(x + (size_t)s1 * FIN))[lane];
        a0.x += v0.x; a0.y += v0.y; a0.z += v0.z; a0.w += v0.w;
        a1.x += v1.x; a1.y += v1.y; a1.z += v1.z; a1.w += v1.w;
    }
    if (i < end) {
        int s0 = __ldg(&g_srcs[i]);
        float4 v0 = ((const float4*)(x + (size_t)s0 * FIN))[lane];
        a0.x += v0.x; a0.y += v0.y; a0.z += v0.z; a0.w += v0.w;
    }
    float inv = 1.0f / fmaxf((float)(end - beg), 1.0f);
    float4 acc;
    acc.x = (a0.x + a1.x) * inv; acc.y = (a0.y + a1.y) * inv;
    acc.z = (a0.z + a1.z) * inv; acc.w = (a0.w + a1.w) * inv;
    ((float4*)(g_agg + (size_t)node * FIN))[lane] = acc;
}

// ---------------- fp16 MMA helper ----------------------------------------------------
#define MMA_F16(d, a, b)                                                          \
    asm volatile("mma.sync.aligned.m16n8k16.row.col.f32.f16.f16.f32 "             \
                 "{%0,%1,%2,%3}, {%4,%5,%6,%7}, {%8,%9}, {%0,%1,%2,%3};"          \
                 : "+f"(d[0]), "+f"(d[1]), "+f"(d[2]), "+f"(d[3])                 \
                 : "r"(a[0]), "r"(a[1]), "r"(a[2]), "r"(a[3]),                    \
                   "r"(b[0]), "r"(b[1]))

__device__ __forceinline__ unsigned pack_h2(float lo, float hi) {
    __half2 h = __floats2half2_rn(lo, hi);
    return *(unsigned*)&h;
}

// ---------------- tensor-core fp16 GEMM, 128x128 tile, BK=64, 8 warps ---------------
// smem layout: row-major half2, row stride 36 words (32 half2 + 4 pad).
// MODE 0: g_h  = relu( norm( [agg | x] @ [W1_l|W1_r]^T + b1 ) )   K=256
// MODE 1: g_h2 = relu( [x | h] @ Wl1^T + bl1 )                    K=256
// MODE 2: [g_t2|g_r2] = g_h2 @ [W2_l ; W2_r]^T                    K=128
#define RS 36   // words per row (half2 units): 32 data + 4 pad

template <int MODE>
__launch_bounds__(256)
__global__ void k_gemm(const float* __restrict__ X,
                       const float* __restrict__ WA,
                       const float* __restrict__ WB,
                       const float* __restrict__ bias) {
    constexpr int KTOT = (MODE == 2) ? 128 : 256;
    constexpr int NC   = KTOT / 64;

    __shared__ unsigned As[128 * RS];
    __shared__ unsigned Ws[128 * RS];
    __shared__ float    rss[128 * 4];

    const int tid  = threadIdx.x;
    const int lane = tid & 31;
    const int w    = tid >> 5;
    const int wm   = w & 1;        // 0..1 (64 rows each)
    const int wn   = w >> 1;       // 0..3 (32 cols each)
    const int qid  = lane >> 2;    // 0..7
    const int tig  = lane & 3;     // 0..3
    const int m0   = blockIdx.x * 128;

    // staging: 8 float4 for A, 8 for W, converted to half2 pairs immediately
    uint2 ra[8], rw[8];

    auto loadA = [&](int k0) {
#pragma unroll
        for (int p = 0; p < 8; p++) {
            int f4 = tid + p * 256;       // 0..2047
            int n  = f4 >> 4;             // row 0..127
            int k  = k0 + (f4 & 15) * 4;  // k within KTOT
            int gm = min(m0 + n, NN - 1); // clamp: garbage rows masked at store
            float4 v;
            if (MODE == 0) {
                if (k < 128) v = *(const float4*)(g_agg + (size_t)gm * 128 + k);
                else         v = *(const float4*)(X     + (size_t)gm * 128 + (k - 128));
            } else if (MODE == 1) {
                if (k < 128) v = *(const float4*)(X   + (size_t)gm * 128 + k);
                else         v = *(const float4*)(g_h + (size_t)gm * 128 + (k - 128));
            } else {
                v = *(const float4*)(g_h2 + (size_t)gm * 128 + k);
            }
            ra[p] = make_uint2(pack_h2(v.x, v.y), pack_h2(v.z, v.w));
        }
    };
    auto loadW = [&](int k0) {
#pragma unroll
        for (int p = 0; p < 8; p++) {
            int f4 = tid + p * 256;
            int j  = f4 >> 4;
            int k  = k0 + (f4 & 15) * 4;
            float4 v;
            if (MODE == 0) {
                v = (k < 128) ? *(const float4*)(WA + j * 128 + k)
                              : *(const float4*)(WB + j * 128 + (k - 128));
            } else if (MODE == 1) {
                v = *(const float4*)(WA + j * 256 + k);
            } else {
                v = (j < 64) ? *(const float4*)(WA + j * 128 + k)
                             : *(const float4*)(WB + (j - 64) * 128 + k);
            }
            rw[p] = make_uint2(pack_h2(v.x, v.y), pack_h2(v.z, v.w));
        }
    };
    auto storeAW = [&]() {
#pragma unroll
        for (int p = 0; p < 8; p++) {
            int f4 = tid + p * 256;
            int n  = f4 >> 4;
            int kq = f4 & 15;             // float4 index -> half2 index kq*2
            *(uint2*)(&As[n * RS + kq * 2]) = ra[p];
            *(uint2*)(&Ws[n * RS + kq * 2]) = rw[p];
        }
    };

    float acc[4][4][4];
#pragma unroll
    for (int mt = 0; mt < 4; mt++)
#pragma unroll
        for (int nt = 0; nt < 4; nt++)
#pragma unroll
            for (int c = 0; c < 4; c++) acc[mt][nt][c] = 0.f;

    loadA(0); loadW(0);

    for (int c = 0; c < NC; c++) {
        __syncthreads();          // smem free (prev MMAs done)
        storeAW();
        __syncthreads();
        if (c + 1 < NC) { loadA((c + 1) * 64); loadW((c + 1) * 64); }  // overlap w/ MMA

#pragma unroll
        for (int ks = 0; ks < 4; ks++) {        // 4 x k16 per 64-chunk
            const int kb = ks * 8;              // half2 base index
            unsigned a[4][4];
#pragma unroll
            for (int mt = 0; mt < 4; mt++) {
                int r0 = wm * 64 + mt * 16 + qid;
                a[mt][0] = As[r0 * RS + kb + tig];
                a[mt][1] = As[(r0 + 8) * RS + kb + tig];
                a[mt][2] = As[r0 * RS + kb + tig + 4];
                a[mt][3] = As[(r0 + 8) * RS + kb + tig + 4];
            }
            unsigned b[4][2];
#pragma unroll
            for (int nt = 0; nt < 4; nt++) {
                int c0 = wn * 32 + nt * 8 + qid;
                b[nt][0] = Ws[c0 * RS + kb + tig];
                b[nt][1] = Ws[c0 * RS + kb + tig + 4];
            }
#pragma unroll
            for (int mt = 0; mt < 4; mt++)
#pragma unroll
                for (int nt = 0; nt < 4; nt++)
                    MMA_F16(acc[mt][nt], a[mt], b[nt]);
        }
    }

    // ---------------- epilogue ----------------
    // row(c) = wm*64 + mt*16 + qid + (c>=2 ? 8 : 0)
    // col(c) = wn*32 + nt*8 + tig*2 + (c&1)
    if (MODE == 0 || MODE == 1) {
#pragma unroll
        for (int nt = 0; nt < 4; nt++) {
            float2 bv = *(const float2*)(bias + wn * 32 + nt * 8 + tig * 2);
#pragma unroll
            for (int mt = 0; mt < 4; mt++) {
                acc[mt][nt][0] += bv.x; acc[mt][nt][1] += bv.y;
                acc[mt][nt][2] += bv.x; acc[mt][nt][3] += bv.y;
            }
        }
    }

    if (MODE == 0) {
        float ssl[4][2];
#pragma unroll
        for (int mt = 0; mt < 4; mt++) {
            float s0 = 0.f, s1 = 0.f;
#pragma unroll
            for (int nt = 0; nt < 4; nt++) {
                s0 += acc[mt][nt][0] * acc[mt][nt][0] + acc[mt][nt][1] * acc[mt][nt][1];
                s1 += acc[mt][nt][2] * acc[mt][nt][2] + acc[mt][nt][3] * acc[mt][nt][3];
            }
            s0 += __shfl_xor_sync(0xffffffffu, s0, 1);
            s0 += __shfl_xor_sync(0xffffffffu, s0, 2);
            s1 += __shfl_xor_sync(0xffffffffu, s1, 1);
            s1 += __shfl_xor_sync(0xffffffffu, s1, 2);
            ssl[mt][0] = s0; ssl[mt][1] = s1;
        }
        __syncthreads();
        if (tig == 0) {
#pragma unroll
            for (int mt = 0; mt < 4; mt++) {
                int r0 = wm * 64 + mt * 16 + qid;
                rss[(r0)     * 4 + wn] = ssl[mt][0];
                rss[(r0 + 8) * 4 + wn] = ssl[mt][1];
            }
        }
        __syncthreads();
#pragma unroll
        for (int mt = 0; mt < 4; mt++) {
#pragma unroll
            for (int h = 0; h < 2; h++) {
                int r = wm * 64 + mt * 16 + qid + h * 8;
                float ss = rss[r * 4 + 0] + rss[r * 4 + 1] + rss[r * 4 + 2] + rss[r * 4 + 3];
                float sc = 1.0f / fmaxf(sqrtf(ss), 1e-12f);
                int gm = m0 + r;
                if (gm < NN) {
#pragma unroll
                    for (int nt = 0; nt < 4; nt++) {
                        float2 o;
                        o.x = fmaxf(acc[mt][nt][h * 2 + 0] * sc, 0.f);
                        o.y = fmaxf(acc[mt][nt][h * 2 + 1] * sc, 0.f);
                        *(float2*)(g_h + (size_t)gm * 128 + wn * 32 + nt * 8 + tig * 2) = o;
                    }
                }
            }
        }
    } else if (MODE == 1) {
#pragma unroll
        for (int mt = 0; mt < 4; mt++) {
#pragma unroll
            for (int h = 0; h < 2; h++) {
                int gm = m0 + wm * 64 + mt * 16 + qid + h * 8;
                if (gm < NN) {
#pragma unroll
                    for (int nt = 0; nt < 4; nt++) {
                        float2 o;
                        o.x = fmaxf(acc[mt][nt][h * 2 + 0], 0.f);
                        o.y = fmaxf(acc[mt][nt][h * 2 + 1], 0.f);
                        *(float2*)(g_h2 + (size_t)gm * 128 + wn * 32 + nt * 8 + tig * 2) = o;
                    }
                }
            }
        }
    } else {
        float* dstbuf = (wn < 2) ? g_t2 : g_r2;
        int coff0 = (wn < 2) ? wn * 32 : (wn - 2) * 32;
#pragma unroll
        for (int mt = 0; mt < 4; mt++) {
#pragma unroll
            for (int h = 0; h < 2; h++) {
                int gm = m0 + wm * 64 + mt * 16 + qid + h * 8;
                if (gm < NN) {
#pragma unroll
                    for (int nt = 0; nt < 4; nt++) {
                        float2 o = make_float2(acc[mt][nt][h * 2 + 0], acc[mt][nt][h * 2 + 1]);
                        *(float2*)(dstbuf + (size_t)gm * 64 + coff0 + nt * 8 + tig * 2) = o;
                    }
                }
            }
        }
    }
}

// ---------------- final: gather t2, out = norm( mean + b2 + r2 ), warp/node ---------
__global__ void k_out(const float* __restrict__ b2, float* __restrict__ out) {
    int node = (blockIdx.x * blockDim.x + threadIdx.x) >> 5;
    int lane = threadIdx.x & 31;
    if (node >= NN) return;
    int beg = g_rowp[node], end = g_rowp[node + 1];
    float2 a0 = make_float2(0.f, 0.f);
    float2 a1 = make_float2(0.f, 0.f);
    int i = beg;
    for (; i + 1 < end; i += 2) {
        int s0 = __ldg(&g_srcs[i]);
        int s1 = __ldg(&g_srcs[i + 1]);
        float2 v0 = ((const float2*)(g_t2 + (size_t)s0 * CC))[lane];
        float2 v1 = ((const float2*)(g_t2 + (size_t)s1 * CC))[lane];
        a0.x += v0.x; a0.y += v0.y;
        a1.x += v1.x; a1.y += v1.y;
    }
    if (i < end) {
        int s0 = __ldg(&g_srcs[i]);
        float2 v0 = ((const float2*)(g_t2 + (size_t)s0 * CC))[lane];
        a0.x += v0.x; a0.y += v0.y;
    }
    float inv = 1.0f / fmaxf((float)(end - beg), 1.0f);
    float2 r  = ((const float2*)(g_r2 + (size_t)node * CC))[lane];
    float2 bb = ((const float2*)b2)[lane];
    float v0 = (a0.x + a1.x) * inv + bb.x + r.x;
    float v1 = (a0.y + a1.y) * inv + bb.y + r.y;
    float ss = v0 * v0 + v1 * v1;
#pragma unroll
    for (int o = 16; o >= 1; o >>= 1) ss += __shfl_xor_sync(0xffffffffu, ss, o);
    float sc = 1.0f / fmaxf(sqrtf(ss), 1e-12f);
    ((float2*)(out + (size_t)node * CC))[lane] = make_float2(v0 * sc, v1 * sc);
}

// ---------------- launch ------------------------------------------------------------
extern "C" void kernel_launch(void* const* d_in, const int* in_sizes, int n_in,
                              void* d_out, int out_size) {
    const float* x    = (const float*)d_in[0];
    const int*   ei   = (const int*)  d_in[1];
    const float* W1_l = (const float*)d_in[2];
    const float* b1   = (const float*)d_in[3];
    const float* W1_r = (const float*)d_in[4];
    const float* Wl1  = (const float*)d_in[5];
    const float* bl1  = (const float*)d_in[6];
    const float* W2_l = (const float*)d_in[7];
    const float* b2   = (const float*)d_in[8];
    const float* W2_r = (const float*)d_in[9];
    float* out = (float*)d_out;

    k_zero  <<<(NN + 255) / 256, 256>>>();
    k_count <<<(EE + 255) / 256, 256>>>(ei);
    k_scan  <<<1, 1024>>>();
    k_bin   <<<(EE / 2 + 255) / 256, 256>>>(ei);
    k_aggr1 <<<(NN * 32 + 255) / 256, 256>>>(x);
    k_gemm<0><<<(NN + 127) / 128, 256>>>(x, W1_l, W1_r, b1);
    k_gemm<1><<<(NN + 127) / 128, 256>>>(x, Wl1, (const float*)nullptr, bl1);
    k_gemm<2><<<(NN + 127) / 128, 256>>>((const float*)nullptr, W2_l, W2_r, (const float*)nullptr);
    k_out   <<<(NN * 32 + 255) / 256, 256>>>(b2, out);
}

// round 7
// speedup vs baseline: 1.4716x; 1.0808x over previous
#include <cuda_runtime.h>
#include <cuda_fp16.h>
#include <math.h>

// Problem constants (fixed by the dataset)
#define NN  50000
#define EE  800000
#define FIN 128
#define HH  128
#define CC  64

// ---------------- device scratch (all feature tensors in half2 words) --------------
__device__ int      g_icnt[NN];
__device__ int      g_rowp[NN + 1];
__device__ int      g_cur [NN];
__device__ int      g_srcs[EE];
__device__ unsigned g_xh  [NN * 64];   // x           (half2)
__device__ unsigned g_aggh[NN * 64];   // mean_aggr(x)(half2)
__device__ unsigned g_hh  [NN * 64];   // h           (half2)
__device__ unsigned g_h2h [NN * 64];   // h2          (half2)
__device__ unsigned g_t2h [NN * 32];   // t2          (half2)
__device__ float    g_r2  [NN * CC];   // h2 @ W2_r^T (f32)
__device__ unsigned g_wh0[128 * 128];  // [W1_l|W1_r] rows of 256 halfs
__device__ unsigned g_wh1[128 * 128];  // Wl1         rows of 256 halfs
__device__ unsigned g_wh2[128 * 64];   // [W2_l;W2_r] rows of 128 halfs

__device__ __forceinline__ unsigned pack_h2(float lo, float hi) {
    __half2 h = __floats2half2_rn(lo, hi);
    return *(unsigned*)&h;
}
__device__ __forceinline__ float2 h2f2(unsigned u) {
    return __half22float2(*(__half2*)&u);
}

// ---------------- x -> fp16 -----------------------------------------------------------
__global__ void k_xhalf(const float* __restrict__ x) {
    int i = blockIdx.x * blockDim.x + threadIdx.x;   // uint2 unit = 4 floats
    if (i < NN * 32) {
        float4 v = ((const float4*)x)[i];
        ((uint2*)g_xh)[i] = make_uint2(pack_h2(v.x, v.y), pack_h2(v.z, v.w));
    }
}

// ---------------- weights -> fp16, pre-packed per GEMM mode ---------------------------
__global__ void k_wconv(const float* __restrict__ W1_l, const float* __restrict__ W1_r,
                        const float* __restrict__ Wl1,
                        const float* __restrict__ W2_l, const float* __restrict__ W2_r) {
    int i = blockIdx.x * blockDim.x + threadIdx.x;   // half2 word index
    if (i < 128 * 128) {                             // wh0: j row, k = 2*(i&127)
        int j = i >> 7, k = (i & 127) * 2;
        float a = (k < 128) ? W1_l[j * 128 + k]     : W1_r[j * 128 + k - 128];
        float b = (k < 128) ? W1_l[j * 128 + k + 1] : W1_r[j * 128 + k + 1 - 128];
        g_wh0[i] = pack_h2(a, b);
        g_wh1[i] = pack_h2(Wl1[j * 256 + k], Wl1[j * 256 + k + 1]);
    }
    if (i < 128 * 64) {                              // wh2: j row (0..127), k = 2*(i&63)
        int j = i >> 6, k = (i & 63) * 2;
        float a = (j < 64) ? W2_l[j * 128 + k]     : W2_r[(j - 64) * 128 + k];
        float b = (j < 64) ? W2_l[j * 128 + k + 1] : W2_r[(j - 64) * 128 + k + 1];
        g_wh2[i] = pack_h2(a, b);
    }
}

// ---------------- degree count + scan + bin (CSR build) -------------------------------
__global__ void k_zero() {
    int i = blockIdx.x * blockDim.x + threadIdx.x;
    if (i < NN) g_icnt[i] = 0;
}

__global__ void k_count(const int* __restrict__ ei) {
    int e = blockIdx.x * blockDim.x + threadIdx.x;
    if (e < EE) atomicAdd(&g_icnt[ei[EE + e]], 1);
}

__global__ __launch_bounds__(1024) void k_scan() {
    __shared__ int sm[1024];
    const int t  = threadIdx.x;
    const int CH = (NN + 1023) / 1024;
    int beg = t * CH;
    int end = min(beg + CH, NN);
    int s = 0;
    for (int i = beg; i < end; i++) s += g_icnt[i];
    sm[t] = s;
    __syncthreads();
#pragma unroll
    for (int o = 1; o < 1024; o <<= 1) {
        int u = (t >= o) ? sm[t - o] : 0;
        __syncthreads();
        sm[t] += u;
        __syncthreads();
    }
    int run = sm[t] - s;
    for (int i = beg; i < end; i++) {
        g_rowp[i] = run;
        g_cur[i]  = run;
        run += g_icnt[i];
    }
    if (t == 1023) g_rowp[NN] = EE;
}

__global__ void k_bin(const int* __restrict__ ei) {
    int e0 = (blockIdx.x * blockDim.x + threadIdx.x) * 2;
#pragma unroll
    for (int q = 0; q < 2; q++) {
        int e = e0 + q;
        if (e < EE) {
            int src = ei[e];
            int dst = ei[EE + e];
            int p = atomicAdd(&g_cur[dst], 1);
            g_srcs[p] = src;
        }
    }
}

// ---------------- layer-1 mean aggregation: warp/node, fp16 gather, f32 accum ---------
__global__ void k_aggr1() {
    int node = (blockIdx.x * blockDim.x + threadIdx.x) >> 5;
    int lane = threadIdx.x & 31;
    if (node >= NN) return;
    int beg = g_rowp[node], end = g_rowp[node + 1];
    float4 a0 = make_float4(0.f, 0.f, 0.f, 0.f);
    float4 a1 = make_float4(0.f, 0.f, 0.f, 0.f);
    int i = beg;
    for (; i + 1 < end; i += 2) {
        int s0 = __ldg(&g_srcs[i]);
        int s1 = __ldg(&g_srcs[i + 1]);
        uint2 u0 = *(const uint2*)(g_xh + (size_t)s0 * 64 + lane * 2);
        uint2 u1 = *(const uint2*)(g_xh + (size_t)s1 * 64 + lane * 2);
        float2 p0 = h2f2(u0.x), p1 = h2f2(u0.y);
        float2 q0 = h2f2(u1.x), q1 = h2f2(u1.y);
        a0.x += p0.x; a0.y += p0.y; a0.z += p1.x; a0.w += p1.y;
        a1.x += q0.x; a1.y += q0.y; a1.z += q1.x; a1.w += q1.y;
    }
    if (i < end) {
        int s0 = __ldg(&g_srcs[i]);
        uint2 u0 = *(const uint2*)(g_xh + (size_t)s0 * 64 + lane * 2);
        float2 p0 = h2f2(u0.x), p1 = h2f2(u0.y);
        a0.x += p0.x; a0.y += p0.y; a0.z += p1.x; a0.w += p1.y;
    }
    float inv = 1.0f / fmaxf((float)(end - beg), 1.0f);
    uint2 o;
    o.x = pack_h2((a0.x + a1.x) * inv, (a0.y + a1.y) * inv);
    o.y = pack_h2((a0.z + a1.z) * inv, (a0.w + a1.w) * inv);
    *(uint2*)(g_aggh + (size_t)node * 64 + lane * 2) = o;
}

// ---------------- fp16 MMA helper ------------------------------------------------------
#define MMA_F16(d, a, b)                                                          \
    asm volatile("mma.sync.aligned.m16n8k16.row.col.f32.f16.f16.f32 "             \
                 "{%0,%1,%2,%3}, {%4,%5,%6,%7}, {%8,%9}, {%0,%1,%2,%3};"          \
                 : "+f"(d[0]), "+f"(d[1]), "+f"(d[2]), "+f"(d[3])                 \
                 : "r"(a[0]), "r"(a[1]), "r"(a[2]), "r"(a[3]),                    \
                   "r"(b[0]), "r"(b[1]))

// ---------------- tensor-core fp16 GEMM, 128x128 tile, BK=64, 8 warps -----------------
// All operands are half2 words in global memory; loaders are raw uint4 copies.
// MODE 0: g_hh  = relu( norm( [agg | x] @ wh0^T + b1 ) )   K=256
// MODE 1: g_h2h = relu( [x | h] @ wh1^T + bl1 )            K=256
// MODE 2: [g_t2h | g_r2] = h2 @ wh2^T                      K=128
#define RS 36   // half2 words per smem row: 32 data + 4 pad

template <int MODE>
__launch_bounds__(256)
__global__ void k_gemm(const float* __restrict__ bias) {
    constexpr int KTOT = (MODE == 2) ? 128 : 256;
    constexpr int NC   = KTOT / 64;
    constexpr int WR   = KTOT / 2;       // weight row stride in words

    __shared__ unsigned As[128 * RS];
    __shared__ unsigned Ws[128 * RS];
    __shared__ float    rss[128 * 4];

    const int tid  = threadIdx.x;
    const int lane = tid & 31;
    const int w    = tid >> 5;
    const int wm   = w & 1;        // 0..1 (64 rows each)
    const int wn   = w >> 1;       // 0..3 (32 cols each)
    const int qid  = lane >> 2;    // 0..7
    const int tig  = lane & 3;     // 0..3
    const int m0   = blockIdx.x * 128;

    uint4 ra4[4], rw4[4];

    auto loadA = [&](int c) {
        const unsigned* base;
        if (MODE == 0)      base = (c < 2) ? g_aggh : g_xh;
        else if (MODE == 1) base = (c < 2) ? g_xh   : g_hh;
        else                base = g_h2h;
        const int offw = (MODE == 2) ? c * 32 : (c & 1) * 32;
#pragma unroll
        for (int p = 0; p < 4; p++) {
            int f   = tid + p * 256;        // 0..1023
            int n   = f >> 3;               // row 0..127
            int seg = f & 7;                // 8-half segment
            int gm  = min(m0 + n, NN - 1);  // clamp; garbage rows masked at store
            ra4[p] = *(const uint4*)(base + (size_t)gm * 64 + offw + seg * 4);
        }
    };
    auto loadW = [&](int c) {
        const unsigned* base = (MODE == 0) ? g_wh0 : (MODE == 1) ? g_wh1 : g_wh2;
        const int offw = c * 32;
#pragma unroll
        for (int p = 0; p < 4; p++) {
            int f   = tid + p * 256;
            int j   = f >> 3;
            int seg = f & 7;
            rw4[p] = *(const uint4*)(base + j * WR + offw + seg * 4);
        }
    };
    auto storeAW = [&]() {
#pragma unroll
        for (int p = 0; p < 4; p++) {
            int f   = tid + p * 256;
            int n   = f >> 3;
            int seg = f & 7;
            *(uint4*)(&As[n * RS + seg * 4]) = ra4[p];
            *(uint4*)(&Ws[n * RS + seg * 4]) = rw4[p];
        }
    };

    float acc[4][4][4];
#pragma unroll
    for (int mt = 0; mt < 4; mt++)
#pragma unroll
        for (int nt = 0; nt < 4; nt++)
#pragma unroll
            for (int c = 0; c < 4; c++) acc[mt][nt][c] = 0.f;

    loadA(0); loadW(0);

    for (int c = 0; c < NC; c++) {
        __syncthreads();
        storeAW();
        __syncthreads();
        if (c + 1 < NC) { loadA(c + 1); loadW(c + 1); }   // overlap next loads with MMA

#pragma unroll
        for (int ks = 0; ks < 4; ks++) {
            const int kb = ks * 8;
            unsigned a[4][4];
#pragma unroll
            for (int mt = 0; mt < 4; mt++) {
                int r0 = wm * 64 + mt * 16 + qid;
                a[mt][0] = As[r0 * RS + kb + tig];
                a[mt][1] = As[(r0 + 8) * RS + kb + tig];
                a[mt][2] = As[r0 * RS + kb + tig + 4];
                a[mt][3] = As[(r0 + 8) * RS + kb + tig + 4];
            }
            unsigned b[4][2];
#pragma unroll
            for (int nt = 0; nt < 4; nt++) {
                int c0 = wn * 32 + nt * 8 + qid;
                b[nt][0] = Ws[c0 * RS + kb + tig];
                b[nt][1] = Ws[c0 * RS + kb + tig + 4];
            }
#pragma unroll
            for (int mt = 0; mt < 4; mt++)
#pragma unroll
                for (int nt = 0; nt < 4; nt++)
                    MMA_F16(acc[mt][nt], a[mt], b[nt]);
        }
    }

    // ---------------- epilogue ----------------
    // row(c) = wm*64 + mt*16 + qid + (c>=2 ? 8 : 0)
    // col(c) = wn*32 + nt*8 + tig*2 + (c&1)
    if (MODE == 0 || MODE == 1) {
#pragma unroll
        for (int nt = 0; nt < 4; nt++) {
            float2 bv = *(const float2*)(bias + wn * 32 + nt * 8 + tig * 2);
#pragma unroll
            for (int mt = 0; mt < 4; mt++) {
                acc[mt][nt][0] += bv.x; acc[mt][nt][1] += bv.y;
                acc[mt][nt][2] += bv.x; acc[mt][nt][3] += bv.y;
            }
        }
    }

    if (MODE == 0) {
        float ssl[4][2];
#pragma unroll
        for (int mt = 0; mt < 4; mt++) {
            float s0 = 0.f, s1 = 0.f;
#pragma unroll
            for (int nt = 0; nt < 4; nt++) {
                s0 += acc[mt][nt][0] * acc[mt][nt][0] + acc[mt][nt][1] * acc[mt][nt][1];
                s1 += acc[mt][nt][2] * acc[mt][nt][2] + acc[mt][nt][3] * acc[mt][nt][3];
            }
            s0 += __shfl_xor_sync(0xffffffffu, s0, 1);
            s0 += __shfl_xor_sync(0xffffffffu, s0, 2);
            s1 += __shfl_xor_sync(0xffffffffu, s1, 1);
            s1 += __shfl_xor_sync(0xffffffffu, s1, 2);
            ssl[mt][0] = s0; ssl[mt][1] = s1;
        }
        __syncthreads();
        if (tig == 0) {
#pragma unroll
            for (int mt = 0; mt < 4; mt++) {
                int r0 = wm * 64 + mt * 16 + qid;
                rss[(r0)     * 4 + wn] = ssl[mt][0];
                rss[(r0 + 8) * 4 + wn] = ssl[mt][1];
            }
        }
        __syncthreads();
#pragma unroll
        for (int mt = 0; mt < 4; mt++) {
#pragma unroll
            for (int h = 0; h < 2; h++) {
                int r = wm * 64 + mt * 16 + qid + h * 8;
                float ss = rss[r * 4 + 0] + rss[r * 4 + 1] + rss[r * 4 + 2] + rss[r * 4 + 3];
                float sc = 1.0f / fmaxf(sqrtf(ss), 1e-12f);
                int gm = m0 + r;
                if (gm < NN) {
#pragma unroll
                    for (int nt = 0; nt < 4; nt++) {
                        float ox = fmaxf(acc[mt][nt][h * 2 + 0] * sc, 0.f);
                        float oy = fmaxf(acc[mt][nt][h * 2 + 1] * sc, 0.f);
                        g_hh[(size_t)gm * 64 + wn * 16 + nt * 4 + tig] = pack_h2(ox, oy);
                    }
                }
            }
        }
    } else if (MODE == 1) {
#pragma unroll
        for (int mt = 0; mt < 4; mt++) {
#pragma unroll
            for (int h = 0; h < 2; h++) {
                int gm = m0 + wm * 64 + mt * 16 + qid + h * 8;
                if (gm < NN) {
#pragma unroll
                    for (int nt = 0; nt < 4; nt++) {
                        float ox = fmaxf(acc[mt][nt][h * 2 + 0], 0.f);
                        float oy = fmaxf(acc[mt][nt][h * 2 + 1], 0.f);
                        g_h2h[(size_t)gm * 64 + wn * 16 + nt * 4 + tig] = pack_h2(ox, oy);
                    }
                }
            }
        }
    } else {
        // cols 0..63 -> t2 (half2), 64..127 -> r2 (f32)
        const bool is_t2 = (wn < 2);
        const int coff0 = is_t2 ? wn * 32 : (wn - 2) * 32;
#pragma unroll
        for (int mt = 0; mt < 4; mt++) {
#pragma unroll
            for (int h = 0; h < 2; h++) {
                int gm = m0 + wm * 64 + mt * 16 + qid + h * 8;
                if (gm < NN) {
#pragma unroll
                    for (int nt = 0; nt < 4; nt++) {
                        float ox = acc[mt][nt][h * 2 + 0];
                        float oy = acc[mt][nt][h * 2 + 1];
                        if (is_t2) {
                            g_t2h[(size_t)gm * 32 + (coff0 >> 1) + nt * 4 + tig] = pack_h2(ox, oy);
                        } else {
                            *(float2*)(g_r2 + (size_t)gm * 64 + coff0 + nt * 8 + tig * 2)
                                = make_float2(ox, oy);
                        }
                    }
                }
            }
        }
    }
}

// ---------------- final: gather t2(half), out = norm( mean + b2 + r2 ), warp/node -----
__global__ void k_out(const float* __restrict__ b2, float* __restrict__ out) {
    int node = (blockIdx.x * blockDim.x + threadIdx.x) >> 5;
    int lane = threadIdx.x & 31;
    if (node >= NN) return;
    int beg = g_rowp[node], end = g_rowp[node + 1];
    float2 a0 = make_float2(0.f, 0.f);
    float2 a1 = make_float2(0.f, 0.f);
    int i = beg;
    for (; i + 1 < end; i += 2) {
        int s0 = __ldg(&g_srcs[i]);
        int s1 = __ldg(&g_srcs[i + 1]);
        float2 v0 = h2f2(__ldg(&g_t2h[(size_t)s0 * 32 + lane]));
        float2 v1 = h2f2(__ldg(&g_t2h[(size_t)s1 * 32 + lane]));
        a0.x += v0.x; a0.y += v0.y;
        a1.x += v1.x; a1.y += v1.y;
    }
    if (i < end) {
        int s0 = __ldg(&g_srcs[i]);
        float2 v0 = h2f2(__ldg(&g_t2h[(size_t)s0 * 32 + lane]));
        a0.x += v0.x; a0.y += v0.y;
    }
    float inv = 1.0f / fmaxf((float)(end - beg), 1.0f);
    float2 r  = ((const float2*)(g_r2 + (size_t)node * CC))[lane];
    float2 bb = ((const float2*)b2)[lane];
    float v0 = (a0.x + a1.x) * inv + bb.x + r.x;
    float v1 = (a0.y + a1.y) * inv + bb.y + r.y;
    float ss = v0 * v0 + v1 * v1;
#pragma unroll
    for (int o = 16; o >= 1; o >>= 1) ss += __shfl_xor_sync(0xffffffffu, ss, o);
    float sc = 1.0f / fmaxf(sqrtf(ss), 1e-12f);
    ((float2*)(out + (size_t)node * CC))[lane] = make_float2(v0 * sc, v1 * sc);
}

// ---------------- launch ----------------------------------------------------------------
extern "C" void kernel_launch(void* const* d_in, const int* in_sizes, int n_in,
                              void* d_out, int out_size) {
    const float* x    = (const float*)d_in[0];
    const int*   ei   = (const int*)  d_in[1];
    const float* W1_l = (const float*)d_in[2];
    const float* b1   = (const float*)d_in[3];
    const float* W1_r = (const float*)d_in[4];
    const float* Wl1  = (const float*)d_in[5];
    const float* bl1  = (const float*)d_in[6];
    const float* W2_l = (const float*)d_in[7];
    const float* b2   = (const float*)d_in[8];
    const float* W2_r = (const float*)d_in[9];
    float* out = (float*)d_out;

    k_xhalf <<<(NN * 32 + 255) / 256, 256>>>(x);
    k_wconv <<<(128 * 128 + 255) / 256, 256>>>(W1_l, W1_r, Wl1, W2_l, W2_r);
    k_zero  <<<(NN + 255) / 256, 256>>>();
    k_count <<<(EE + 255) / 256, 256>>>(ei);
    k_scan  <<<1, 1024>>>();
    k_bin   <<<(EE / 2 + 255) / 256, 256>>>(ei);
    k_aggr1 <<<(NN * 32 + 255) / 256, 256>>>();
    k_gemm<0><<<(NN + 127) / 128, 256>>>(b1);
    k_gemm<1><<<(NN + 127) / 128, 256>>>(bl1);
    k_gemm<2><<<(NN + 127) / 128, 256>>>(b2);   // bias unused in MODE 2 path
    k_out   <<<(NN * 32 + 255) / 256, 256>>>(b2, out);
}

// round 9
// speedup vs baseline: 1.6003x; 1.0875x over previous
#include <cuda_runtime.h>
#include <cuda_fp16.h>
#include <math.h>

// Problem constants (fixed by the dataset)
#define NN  50000
#define EE  800000
#define FIN 128
#define HH  128
#define CC  64

// ---------------- device scratch (feature tensors in half2 words) -------------------
__device__ int      g_icnt[NN];
__device__ int      g_rowp[NN + 1];
__device__ int      g_cur [NN];
__device__ int      g_srcs[EE];
__device__ unsigned g_xh  [NN * 64];   // x           (half2)
__device__ unsigned g_aggh[NN * 64];   // mean_aggr(x)(half2)
__device__ unsigned g_t2h [NN * 32];   // t2          (half2)
__device__ float    g_r2  [NN * CC];   // h2 @ W2_r^T (f32)
__device__ unsigned g_wh0[128 * 128];  // [W1_l|W1_r] rows of 256 halfs
__device__ unsigned g_wh1[128 * 128];  // Wl1         rows of 256 halfs
__device__ unsigned g_wh2[128 * 64];   // [W2_l;W2_r] rows of 128 halfs

__device__ __forceinline__ unsigned pack_h2(float lo, float hi) {
    __half2 h = __floats2half2_rn(lo, hi);
    return *(unsigned*)&h;
}
__device__ __forceinline__ float2 h2f2(unsigned u) {
    return __half22float2(*(__half2*)&u);
}

// ---------------- x -> fp16 -----------------------------------------------------------
__global__ void k_xhalf(const float* __restrict__ x) {
    int i = blockIdx.x * blockDim.x + threadIdx.x;   // uint2 unit = 4 floats
    if (i < NN * 32) {
        float4 v = ((const float4*)x)[i];
        ((uint2*)g_xh)[i] = make_uint2(pack_h2(v.x, v.y), pack_h2(v.z, v.w));
    }
}

// ---------------- weights -> fp16, pre-packed per GEMM mode ---------------------------
__global__ void k_wconv(const float* __restrict__ W1_l, const float* __restrict__ W1_r,
                        const float* __restrict__ Wl1,
                        const float* __restrict__ W2_l, const float* __restrict__ W2_r) {
    int i = blockIdx.x * blockDim.x + threadIdx.x;   // half2 word index
    if (i < 128 * 128) {
        int j = i >> 7, k = (i & 127) * 2;
        float a = (k < 128) ? W1_l[j * 128 + k]     : W1_r[j * 128 + k - 128];
        float b = (k < 128) ? W1_l[j * 128 + k + 1] : W1_r[j * 128 + k + 1 - 128];
        g_wh0[i] = pack_h2(a, b);
        g_wh1[i] = pack_h2(Wl1[j * 256 + k], Wl1[j * 256 + k + 1]);
    }
    if (i < 128 * 64) {
        int j = i >> 6, k = (i & 63) * 2;
        float a = (j < 64) ? W2_l[j * 128 + k]     : W2_r[(j - 64) * 128 + k];
        float b = (j < 64) ? W2_l[j * 128 + k + 1] : W2_r[(j - 64) * 128 + k + 1];
        g_wh2[i] = pack_h2(a, b);
    }
}

// ---------------- degree count + scan + bin (CSR build) -------------------------------
__global__ void k_zero() {
    int i = blockIdx.x * blockDim.x + threadIdx.x;
    if (i < NN) g_icnt[i] = 0;
}

__global__ void k_count(const int* __restrict__ ei) {
    int e = blockIdx.x * blockDim.x + threadIdx.x;
    if (e < EE) atomicAdd(&g_icnt[ei[EE + e]], 1);
}

__global__ __launch_bounds__(1024) void k_scan() {
    __shared__ int sm[1024];
    const int t  = threadIdx.x;
    const int CH = (NN + 1023) / 1024;
    int beg = t * CH;
    int end = min(beg + CH, NN);
    int s = 0;
    for (int i = beg; i < end; i++) s += g_icnt[i];
    sm[t] = s;
    __syncthreads();
#pragma unroll
    for (int o = 1; o < 1024; o <<= 1) {
        int u = (t >= o) ? sm[t - o] : 0;
        __syncthreads();
        sm[t] += u;
        __syncthreads();
    }
    int run = sm[t] - s;
    for (int i = beg; i < end; i++) {
        g_rowp[i] = run;
        g_cur[i]  = run;
        run += g_icnt[i];
    }
    if (t == 1023) g_rowp[NN] = EE;
}

__global__ void k_bin(const int* __restrict__ ei) {
    int e0 = (blockIdx.x * blockDim.x + threadIdx.x) * 2;
#pragma unroll
    for (int q = 0; q < 2; q++) {
        int e = e0 + q;
        if (e < EE) {
            int src = ei[e];
            int dst = ei[EE + e];
            int p = atomicAdd(&g_cur[dst], 1);
            g_srcs[p] = src;
        }
    }
}

// ---------------- layer-1 mean aggregation: warp/node, fp16 gather, f32 accum ---------
__global__ void k_aggr1() {
    int node = (blockIdx.x * blockDim.x + threadIdx.x) >> 5;
    int lane = threadIdx.x & 31;
    if (node >= NN) return;
    int beg = g_rowp[node], end = g_rowp[node + 1];
    float4 a0 = make_float4(0.f, 0.f, 0.f, 0.f);
    float4 a1 = make_float4(0.f, 0.f, 0.f, 0.f);
    int i = beg;
    for (; i + 1 < end; i += 2) {
        int s0 = __ldg(&g_srcs[i]);
        int s1 = __ldg(&g_srcs[i + 1]);
        uint2 u0 = *(const uint2*)(g_xh + (size_t)s0 * 64 + lane * 2);
        uint2 u1 = *(const uint2*)(g_xh + (size_t)s1 * 64 + lane * 2);
        float2 p0 = h2f2(u0.x), p1 = h2f2(u0.y);
        float2 q0 = h2f2(u1.x), q1 = h2f2(u1.y);
        a0.x += p0.x; a0.y += p0.y; a0.z += p1.x; a0.w += p1.y;
        a1.x += q0.x; a1.y += q0.y; a1.z += q1.x; a1.w += q1.y;
    }
    if (i < end) {
        int s0 = __ldg(&g_srcs[i]);
        uint2 u0 = *(const uint2*)(g_xh + (size_t)s0 * 64 + lane * 2);
        float2 p0 = h2f2(u0.x), p1 = h2f2(u0.y);
        a0.x += p0.x; a0.y += p0.y; a0.z += p1.x; a0.w += p1.y;
    }
    float inv = 1.0f / fmaxf((float)(end - beg), 1.0f);
    uint2 o;
    o.x = pack_h2((a0.x + a1.x) * inv, (a0.y + a1.y) * inv);
    o.y = pack_h2((a0.z + a1.z) * inv, (a0.w + a1.w) * inv);
    *(uint2*)(g_aggh + (size_t)node * 64 + lane * 2) = o;
}

// ---------------- fp16 MMA helper ------------------------------------------------------
#define MMA_F16(d, a, b)                                                          \
    asm volatile("mma.sync.aligned.m16n8k16.row.col.f32.f16.f16.f32 "             \
                 "{%0,%1,%2,%3}, {%4,%5,%6,%7}, {%8,%9}, {%0,%1,%2,%3};"          \
                 : "+f"(d[0]), "+f"(d[1]), "+f"(d[2]), "+f"(d[3])                 \
                 : "r"(a[0]), "r"(a[1]), "r"(a[2]), "r"(a[3]),                    \
                   "r"(b[0]), "r"(b[1]))

// ---------------- FUSED 3-GEMM kernel --------------------------------------------------
// Per CTA: 128 nodes. A operand lives in smem for the whole kernel:
//   XA words 0..63  = agg   (later overwritten by h, then h2)
//   XA words 64..127= x     (resident, reused by GEMM0 and GEMM1)
// GEMM0: [agg|x]@wh0^T -> +b1, L2-norm, relu -> h   -> XA[0..63]
// GEMM1: [x|h] @wh1^T -> +bl1, relu         -> h2  -> XA[0..63]
// GEMM2: h2    @wh2^T -> t2 (half, cols 0..63) + r2 (f32, cols 64..127)
// Weights stream through Ws (one 64-K chunk) with register prefetch; 10 chunks total.
#define RSX 132   // XA row stride in half2 words (132 % 32 == 4 -> conflict-free)
#define RSW 36    // Ws row stride in half2 words
#define FUSED_SMEM ((128 * RSX + 128 * RSW) * 4 + 512 * 4 + 256 * 4)

__global__ __launch_bounds__(256)
void k_fused(const float* __restrict__ b1, const float* __restrict__ bl1) {
    extern __shared__ unsigned smem[];
    unsigned* XA  = smem;                       // 128*132 words
    unsigned* Ws  = smem + 128 * RSX;           // 128*36 words
    float*    rss = (float*)(Ws + 128 * RSW);   // 512 floats
    float*    bsm = rss + 512;                  // 256 floats: b1 | bl1

    const int tid  = threadIdx.x;
    const int lane = tid & 31;
    const int w    = tid >> 5;
    const int wm   = w & 1;        // 0..1 (64 rows each)
    const int wn   = w >> 1;       // 0..3 (32 cols each)
    const int qid  = lane >> 2;    // 0..7
    const int tig  = lane & 3;     // 0..3
    const int m0   = blockIdx.x * 128;

    bsm[tid] = (tid < 128) ? b1[tid] : bl1[tid - 128];

    // ---- fill XA: words 0..63 = agg, 64..127 = x ----
#pragma unroll
    for (int p = 0; p < 16; p++) {
        int f    = tid + p * 256;        // 0..4095
        int row  = f >> 5;               // 0..127
        int word = (f & 31) * 4;         // uint4-aligned word 0..124
        int gm   = min(m0 + row, NN - 1);
        uint4 v = (word < 64)
            ? *(const uint4*)(g_aggh + (size_t)gm * 64 + word)
            : *(const uint4*)(g_xh   + (size_t)gm * 64 + (word - 64));
        *(uint4*)(&XA[row * RSX + word]) = v;
    }

    // ---- weight chunk streaming ----
    uint4 rw4[4];
    auto loadW = [&](int idx) {   // flat chunk idx 0..9
        const unsigned* base; int WR, off;
        if (idx < 4)      { base = g_wh0; WR = 128; off = idx * 32; }
        else if (idx < 8) { base = g_wh1; WR = 128; off = (idx - 4) * 32; }
        else              { base = g_wh2; WR = 64;  off = (idx - 8) * 32; }
#pragma unroll
        for (int p = 0; p < 4; p++) {
            int f = tid + p * 256;
            int j = f >> 3, seg = f & 7;
            rw4[p] = *(const uint4*)(base + j * WR + off + seg * 4);
        }
    };
    auto storeW = [&]() {
#pragma unroll
        for (int p = 0; p < 4; p++) {
            int f = tid + p * 256;
            int j = f >> 3, seg = f & 7;
            *(uint4*)(&Ws[j * RSW + seg * 4]) = rw4[p];
        }
    };

    float acc[4][4][4];
    auto resetAcc = [&]() {
#pragma unroll
        for (int mt = 0; mt < 4; mt++)
#pragma unroll
            for (int nt = 0; nt < 4; nt++)
#pragma unroll
                for (int c = 0; c < 4; c++) acc[mt][nt][c] = 0.f;
    };

    int widx = 0;
    loadW(0); widx = 1;

    auto runChunks = [&](int nch, int gsel) {
        for (int c = 0; c < nch; c++) {
            __syncthreads();
            storeW();
            __syncthreads();
            if (widx < 10) { loadW(widx); widx++; }
            int offA = (gsel == 1) ? ((c < 2) ? 64 + c * 32 : (c - 2) * 32)
                                   : c * 32;
#pragma unroll
            for (int ks = 0; ks < 4; ks++) {
                const int kb = ks * 8;
                unsigned a[4][4];
#pragma unroll
                for (int mt = 0; mt < 4; mt++) {
                    int r0 = wm * 64 + mt * 16 + qid;
                    a[mt][0] = XA[r0 * RSX + offA + kb + tig];
                    a[mt][1] = XA[(r0 + 8) * RSX + offA + kb + tig];
                    a[mt][2] = XA[r0 * RSX + offA + kb + tig + 4];
                    a[mt][3] = XA[(r0 + 8) * RSX + offA + kb + tig + 4];
                }
                unsigned b[4][2];
#pragma unroll
                for (int nt = 0; nt < 4; nt++) {
                    int c0 = wn * 32 + nt * 8 + qid;
                    b[nt][0] = Ws[c0 * RSW + kb + tig];
                    b[nt][1] = Ws[c0 * RSW + kb + tig + 4];
                }
#pragma unroll
                for (int mt = 0; mt < 4; mt++)
#pragma unroll
                    for (int nt = 0; nt < 4; nt++)
                        MMA_F16(acc[mt][nt], a[mt], b[nt]);
            }
        }
    };

    // ================= GEMM0: [agg|x] @ wh0^T =================
    resetAcc();
    runChunks(4, 0);

    // epilogue0: +b1, L2 row-norm, relu, h -> XA words 0..63
    {
#pragma unroll
        for (int nt = 0; nt < 4; nt++) {
            float bx = bsm[wn * 32 + nt * 8 + tig * 2];
            float by = bsm[wn * 32 + nt * 8 + tig * 2 + 1];
#pragma unroll
            for (int mt = 0; mt < 4; mt++) {
                acc[mt][nt][0] += bx; acc[mt][nt][1] += by;
                acc[mt][nt][2] += bx; acc[mt][nt][3] += by;
            }
        }
        float ssl[4][2];
#pragma unroll
        for (int mt = 0; mt < 4; mt++) {
            float s0 = 0.f, s1 = 0.f;
#pragma unroll
            for (int nt = 0; nt < 4; nt++) {
                s0 += acc[mt][nt][0] * acc[mt][nt][0] + acc[mt][nt][1] * acc[mt][nt][1];
                s1 += acc[mt][nt][2] * acc[mt][nt][2] + acc[mt][nt][3] * acc[mt][nt][3];
            }
            s0 += __shfl_xor_sync(0xffffffffu, s0, 1);
            s0 += __shfl_xor_sync(0xffffffffu, s0, 2);
            s1 += __shfl_xor_sync(0xffffffffu, s1, 1);
            s1 += __shfl_xor_sync(0xffffffffu, s1, 2);
            ssl[mt][0] = s0; ssl[mt][1] = s1;
        }
        if (tig == 0) {
#pragma unroll
            for (int mt = 0; mt < 4; mt++) {
                int r0 = wm * 64 + mt * 16 + qid;
                rss[(r0)     * 4 + wn] = ssl[mt][0];
                rss[(r0 + 8) * 4 + wn] = ssl[mt][1];
            }
        }
        __syncthreads();   // also guarantees all GEMM0 MMAs done before XA[0..63] overwrite
#pragma unroll
        for (int mt = 0; mt < 4; mt++) {
#pragma unroll
            for (int h = 0; h < 2; h++) {
                int r = wm * 64 + mt * 16 + qid + h * 8;
                float ss = rss[r * 4 + 0] + rss[r * 4 + 1] + rss[r * 4 + 2] + rss[r * 4 + 3];
                float scl = 1.0f / fmaxf(sqrtf(ss), 1e-12f);
#pragma unroll
                for (int nt = 0; nt < 4; nt++) {
                    float ox = fmaxf(acc[mt][nt][h * 2 + 0] * scl, 0.f);
                    float oy = fmaxf(acc[mt][nt][h * 2 + 1] * scl, 0.f);
                    XA[r * RSX + wn * 16 + nt * 4 + tig] = pack_h2(ox, oy);
                }
            }
        }
    }

    // ================= GEMM1: [x|h] @ wh1^T =================
    resetAcc();
    runChunks(4, 1);

    // epilogue1: +bl1, relu, h2 -> XA words 0..63
    __syncthreads();   // all GEMM1 MMAs done before overwriting h
    {
#pragma unroll
        for (int mt = 0; mt < 4; mt++) {
#pragma unroll
            for (int h = 0; h < 2; h++) {
                int r = wm * 64 + mt * 16 + qid + h * 8;
#pragma unroll
                for (int nt = 0; nt < 4; nt++) {
                    float bx = bsm[128 + wn * 32 + nt * 8 + tig * 2];
                    float by = bsm[128 + wn * 32 + nt * 8 + tig * 2 + 1];
                    float ox = fmaxf(acc[mt][nt][h * 2 + 0] + bx, 0.f);
                    float oy = fmaxf(acc[mt][nt][h * 2 + 1] + by, 0.f);
                    XA[r * RSX + wn * 16 + nt * 4 + tig] = pack_h2(ox, oy);
                }
            }
        }
    }

    // ================= GEMM2: h2 @ wh2^T =================
    resetAcc();
    runChunks(2, 2);

    // epilogue2: cols 0..63 -> t2 (half2), 64..127 -> r2 (f32)
    {
        const bool is_t2 = (wn < 2);
        const int coff0 = is_t2 ? wn * 32 : (wn - 2) * 32;
#pragma unroll
        for (int mt = 0; mt < 4; mt++) {
#pragma unroll
            for (int h = 0; h < 2; h++) {
                int gm = m0 + wm * 64 + mt * 16 + qid + h * 8;
                if (gm < NN) {
#pragma unroll
                    for (int nt = 0; nt < 4; nt++) {
                        float ox = acc[mt][nt][h * 2 + 0];
                        float oy = acc[mt][nt][h * 2 + 1];
                        if (is_t2) {
                            g_t2h[(size_t)gm * 32 + (coff0 >> 1) + nt * 4 + tig] = pack_h2(ox, oy);
                        } else {
                            *(float2*)(g_r2 + (size_t)gm * 64 + coff0 + nt * 8 + tig * 2)
                                = make_float2(ox, oy);
                        }
                    }
                }
            }
        }
    }
}

// ---------------- final: gather t2(half), out = norm( mean + b2 + r2 ), warp/node -----
__global__ void k_out(const float* __restrict__ b2, float* __restrict__ out) {
    int node = (blockIdx.x * blockDim.x + threadIdx.x) >> 5;
    int lane = threadIdx.x & 31;
    if (node >= NN) return;
    int beg = g_rowp[node], end = g_rowp[node + 1];
    float2 a0 = make_float2(0.f, 0.f);
    float2 a1 = make_float2(0.f, 0.f);
    int i = beg;
    for (; i + 1 < end; i += 2) {
        int s0 = __ldg(&g_srcs[i]);
        int s1 = __ldg(&g_srcs[i + 1]);
        float2 v0 = h2f2(__ldg(&g_t2h[(size_t)s0 * 32 + lane]));
        float2 v1 = h2f2(__ldg(&g_t2h[(size_t)s1 * 32 + lane]));
        a0.x += v0.x; a0.y += v0.y;
        a1.x += v1.x; a1.y += v1.y;
    }
    if (i < end) {
        int s0 = __ldg(&g_srcs[i]);
        float2 v0 = h2f2(__ldg(&g_t2h[(size_t)s0 * 32 + lane]));
        a0.x += v0.x; a0.y += v0.y;
    }
    float inv = 1.0f / fmaxf((float)(end - beg), 1.0f);
    float2 r  = ((const float2*)(g_r2 + (size_t)node * CC))[lane];
    float2 bb = ((const float2*)b2)[lane];
    float v0 = (a0.x + a1.x) * inv + bb.x + r.x;
    float v1 = (a0.y + a1.y) * inv + bb.y + r.y;
    float ss = v0 * v0 + v1 * v1;
#pragma unroll
    for (int o = 16; o >= 1; o >>= 1) ss += __shfl_xor_sync(0xffffffffu, ss, o);
    float sc = 1.0f / fmaxf(sqrtf(ss), 1e-12f);
    ((float2*)(out + (size_t)node * CC))[lane] = make_float2(v0 * sc, v1 * sc);
}

// ---------------- launch ----------------------------------------------------------------
extern "C" void kernel_launch(void* const* d_in, const int* in_sizes, int n_in,
                              void* d_out, int out_size) {
    const float* x    = (const float*)d_in[0];
    const int*   ei   = (const int*)  d_in[1];
    const float* W1_l = (const float*)d_in[2];
    const float* b1   = (const float*)d_in[3];
    const float* W1_r = (const float*)d_in[4];
    const float* Wl1  = (const float*)d_in[5];
    const float* bl1  = (const float*)d_in[6];
    const float* W2_l = (const float*)d_in[7];
    const float* b2   = (const float*)d_in[8];
    const float* W2_r = (const float*)d_in[9];
    float* out = (float*)d_out;

    static bool attr_done = false;
    if (!attr_done) {
        cudaFuncSetAttribute(k_fused, cudaFuncAttributeMaxDynamicSharedMemorySize, FUSED_SMEM);
        attr_done = true;
    }

    k_xhalf <<<(NN * 32 + 255) / 256, 256>>>(x);
    k_wconv <<<(128 * 128 + 255) / 256, 256>>>(W1_l, W1_r, Wl1, W2_l, W2_r);
    k_zero  <<<(NN + 255) / 256, 256>>>();
    k_count <<<(EE + 255) / 256, 256>>>(ei);
    k_scan  <<<1, 1024>>>();
    k_bin   <<<(EE / 2 + 255) / 256, 256>>>(ei);
    k_aggr1 <<<(NN * 32 + 255) / 256, 256>>>();
    k_fused <<<(NN + 127) / 128, 256, FUSED_SMEM>>>(b1, bl1);
    k_out   <<<(NN * 32 + 255) / 256, 256>>>(b2, out);
}